// round 1
// baseline (speedup 1.0000x reference)
#include <cuda_runtime.h>
#include <math.h>

#define BATCH 4
#define CH    384
#define IMG   128
#define HWN   (IMG*IMG)      // 16384
#define NH    8
#define HD    48             // CH/NH
#define NBH   (BATCH*NH)     // 32
#define GRAM_CHUNKS 32
#define NCHUNK (HWN/GRAM_CHUNKS)  // 512

// ---------------- scratch (device globals; no allocation) ----------------
__device__ __align__(16) float g_pre  [3ull*BATCH*CH*HWN];  // [slot][b][c][p] slot0=q_m,1=k,2=v (pre-dw)
__device__ __align__(16) float g_post [3ull*BATCH*CH*HWN];  // after depthwise conv
__device__ __align__(16) float g_sqn  [2*BATCH*CH];         // squared norms of q (z<4) and k (z>=4) rows
__device__ __align__(16) float g_gpart[(size_t)GRAM_CHUNKS*NBH*HD*HD];
__device__ __align__(16) float g_gram [NBH*HD*HD];          // gram -> (in place) softmaxed attention
__device__ __align__(16) float g_attnout[(size_t)BATCH*CH*HWN];

// ---------------- 128x128x16 fp32 SGEMM tile (K=384, N=HWN) ----------------
__device__ __forceinline__ void sgemm_tile_384(
    const float* __restrict__ W,   // M x 384 row-major, use rows [by*128, by*128+128)
    const float* __restrict__ X,   // 384 x HWN row-major
    float*       __restrict__ Y)   // M x HWN row-major
{
    __shared__ __align__(16) float As[16][128];
    __shared__ __align__(16) float Bs[16][128];

    const int tid = threadIdx.x;           // 256 threads
    const int tx  = tid & 15;
    const int ty  = tid >> 4;
    const int row0 = blockIdx.y * 128;
    const int col0 = blockIdx.x * 128;

    const int a_r = tid >> 2;              // 0..63
    const int a_c = (tid & 3) << 2;        // 0,4,8,12
    const int b_r = tid >> 5;              // 0..7
    const int b_c = (tid & 31) << 2;       // 0..124

    float acc[8][8];
#pragma unroll
    for (int i = 0; i < 8; i++)
#pragma unroll
        for (int j = 0; j < 8; j++) acc[i][j] = 0.f;

    for (int k0 = 0; k0 < 384; k0 += 16) {
#pragma unroll
        for (int s = 0; s < 2; s++) {
            const float4 w4 = *(const float4*)&W[(size_t)(row0 + a_r + s*64)*384 + k0 + a_c];
            As[a_c+0][a_r + s*64] = w4.x;
            As[a_c+1][a_r + s*64] = w4.y;
            As[a_c+2][a_r + s*64] = w4.z;
            As[a_c+3][a_r + s*64] = w4.w;
        }
#pragma unroll
        for (int s = 0; s < 2; s++) {
            *(float4*)&Bs[b_r + s*8][b_c] =
                *(const float4*)&X[(size_t)(k0 + b_r + s*8)*HWN + col0 + b_c];
        }
        __syncthreads();

#pragma unroll
        for (int kk = 0; kk < 16; kk++) {
            float a[8], bb[8];
            *(float4*)&a[0]  = *(const float4*)&As[kk][ty*8];
            *(float4*)&a[4]  = *(const float4*)&As[kk][ty*8 + 4];
            *(float4*)&bb[0] = *(const float4*)&Bs[kk][tx*8];
            *(float4*)&bb[4] = *(const float4*)&Bs[kk][tx*8 + 4];
#pragma unroll
            for (int i = 0; i < 8; i++)
#pragma unroll
                for (int j = 0; j < 8; j++) acc[i][j] += a[i] * bb[j];
        }
        __syncthreads();
    }

#pragma unroll
    for (int i = 0; i < 8; i++) {
        float* dst = &Y[(size_t)(row0 + ty*8 + i)*HWN + col0 + tx*8];
        *(float4*)&dst[0] = make_float4(acc[i][0], acc[i][1], acc[i][2], acc[i][3]);
        *(float4*)&dst[4] = make_float4(acc[i][4], acc[i][5], acc[i][6], acc[i][7]);
    }
}

// slot s, batch b packed as z = s*BATCH + b
__global__ __launch_bounds__(256)
void qkv_gemm_kernel(const float* __restrict__ x, const float* __restrict__ msg,
                     const float* __restrict__ w_qkv)
{
    const int z = blockIdx.z;
    const int s = z / BATCH;           // 0:q(from message) 1:k 2:v
    const int b = z % BATCH;
    const float* W = w_qkv + (size_t)s * CH * CH;
    const float* X = ((s == 0) ? msg : x) + (size_t)b * CH * HWN;
    float*       Y = g_pre + (size_t)z * CH * HWN;
    sgemm_tile_384(W, X, Y);
}

__global__ __launch_bounds__(256)
void proj_gemm_kernel(const float* __restrict__ w_proj, float* __restrict__ out)
{
    const int b = blockIdx.z;
    const float* X = g_attnout + (size_t)b * CH * HWN;
    float*       Y = out       + (size_t)b * CH * HWN;
    sgemm_tile_384(w_proj, X, Y);
}

// ---------------- depthwise 3x3, SAME, cross-correlation ----------------
__global__ __launch_bounds__(256)
void dwconv_kernel(const float* __restrict__ wdw)
{
    const int zc = blockIdx.z;            // z*CH + c
    const int z  = zc / CH;
    const int c  = zc % CH;
    const int s  = z / BATCH;
    const float* wk = wdw + (size_t)(s*CH + c) * 9;
    const float* in  = g_pre  + (size_t)zc * HWN;
    float*       outp = g_post + (size_t)zc * HWN;

    float w[9];
#pragma unroll
    for (int i = 0; i < 9; i++) w[i] = wk[i];

    const int px = blockIdx.x * 32 + threadIdx.x;
    const int py = blockIdx.y * 8  + threadIdx.y;
    float acc = 0.f;
#pragma unroll
    for (int ky = 0; ky < 3; ky++) {
        const int iy = py + ky - 1;
        if (iy < 0 || iy >= IMG) continue;
#pragma unroll
        for (int kx = 0; kx < 3; kx++) {
            const int ix = px + kx - 1;
            if (ix < 0 || ix >= IMG) continue;
            acc += __ldg(&in[iy*IMG + ix]) * w[ky*3 + kx];
        }
    }
    outp[py*IMG + px] = acc;
}

// ---------------- squared norms of q_m and k rows ----------------
__global__ __launch_bounds__(256)
void sqnorm_kernel()
{
    const int r = blockIdx.x;                  // 0 .. 2*BATCH*CH-1 (slots 0,1 of g_post)
    const float* p = g_post + (size_t)r * HWN;
    const int tid = threadIdx.x;
    float s = 0.f;
    for (int i = tid*4; i < HWN; i += 256*4) {
        float4 v = *(const float4*)&p[i];
        s += v.x*v.x + v.y*v.y + v.z*v.z + v.w*v.w;
    }
    // block reduce
    __shared__ float red[8];
#pragma unroll
    for (int o = 16; o > 0; o >>= 1) s += __shfl_xor_sync(0xffffffffu, s, o);
    if ((tid & 31) == 0) red[tid >> 5] = s;
    __syncthreads();
    if (tid == 0) {
        float t = 0.f;
#pragma unroll
        for (int i = 0; i < 8; i++) t += red[i];
        g_sqn[r] = t;
    }
}

// ---------------- Gram partials: G[bh][i][j] += sum_n q[i,n]*k[j,n] ----------------
__global__ __launch_bounds__(256)
void gram_kernel()
{
    __shared__ __align__(16) float qs[48][65];
    __shared__ __align__(16) float ks[48][65];

    const int bh = blockIdx.y;
    const int b  = bh >> 3;
    const int h  = bh & 7;
    const int n0 = blockIdx.x * NCHUNK;
    const float* qbase = g_post + ((size_t)(0*BATCH + b)*CH + h*HD) * HWN;
    const float* kbase = g_post + ((size_t)(1*BATCH + b)*CH + h*HD) * HWN;
    const int tid = threadIdx.y * 16 + threadIdx.x;

    float acc[3][3];
#pragma unroll
    for (int r = 0; r < 3; r++)
#pragma unroll
        for (int c = 0; c < 3; c++) acc[r][c] = 0.f;

    const int i0 = threadIdx.y * 3;
    const int j0 = threadIdx.x * 3;

    for (int t = 0; t < NCHUNK; t += 64) {
        for (int e = tid; e < 48*64; e += 256) {
            const int i = e >> 6, j = e & 63;
            qs[i][j] = qbase[(size_t)i*HWN + n0 + t + j];
            ks[i][j] = kbase[(size_t)i*HWN + n0 + t + j];
        }
        __syncthreads();
#pragma unroll 8
        for (int nn = 0; nn < 64; nn++) {
            const float q0 = qs[i0+0][nn], q1 = qs[i0+1][nn], q2 = qs[i0+2][nn];
            const float k0 = ks[j0+0][nn], k1 = ks[j0+1][nn], k2 = ks[j0+2][nn];
            acc[0][0] += q0*k0; acc[0][1] += q0*k1; acc[0][2] += q0*k2;
            acc[1][0] += q1*k0; acc[1][1] += q1*k1; acc[1][2] += q1*k2;
            acc[2][0] += q2*k0; acc[2][1] += q2*k1; acc[2][2] += q2*k2;
        }
        __syncthreads();
    }

    float* gp = g_gpart + ((size_t)blockIdx.x * NBH + bh) * (HD*HD);
#pragma unroll
    for (int r = 0; r < 3; r++)
#pragma unroll
        for (int c = 0; c < 3; c++)
            gp[(i0+r)*HD + (j0+c)] = acc[r][c];
}

__global__ __launch_bounds__(1024)
void gram_reduce_kernel()
{
    const int idx = blockIdx.x * 1024 + threadIdx.x;   // < NBH*2304
    float s = 0.f;
#pragma unroll
    for (int ch = 0; ch < GRAM_CHUNKS; ch++)
        s += g_gpart[(size_t)ch * NBH * (HD*HD) + idx];
    g_gram[idx] = s;
}

// ---------------- normalize, temperature, softmax over j (48) ----------------
__global__ __launch_bounds__(64)
void softmax_kernel(const float* __restrict__ temp)
{
    const int bh = blockIdx.x;
    const int b  = bh >> 3;
    const int h  = bh & 7;
    const int i  = threadIdx.x;
    if (i >= HD) return;

    float* gg = g_gram + (size_t)bh * (HD*HD) + i*HD;
    const float invq = rsqrtf(fmaxf(g_sqn[b*CH + h*HD + i], 1e-24f));
    const float T = temp[h];

    float row[HD];
    float m = -3.4e38f;
#pragma unroll
    for (int j = 0; j < HD; j++) {
        const float invk = rsqrtf(fmaxf(g_sqn[(BATCH + b)*CH + h*HD + j], 1e-24f));
        const float v = gg[j] * invq * invk * T;
        row[j] = v;
        m = fmaxf(m, v);
    }
    float sum = 0.f;
#pragma unroll
    for (int j = 0; j < HD; j++) { row[j] = expf(row[j] - m); sum += row[j]; }
    const float inv = 1.f / sum;
#pragma unroll
    for (int j = 0; j < HD; j++) gg[j] = row[j] * inv;
}

// ---------------- out[b,h,i,n] = sum_j A[i,j] * v[b,h,j,n] ----------------
__global__ __launch_bounds__(256)
void av_kernel()
{
    __shared__ __align__(16) float As[HD*HD];
    const int bh = blockIdx.y;
    const int b  = bh >> 3;
    const int h  = bh & 7;
    const int tid = threadIdx.x;
    const int n = blockIdx.x * 256 + tid;

    for (int e = tid; e < HD*HD; e += 256) As[e] = g_gram[(size_t)bh * (HD*HD) + e];
    __syncthreads();

    const float* vbase = g_post + ((size_t)(2*BATCH + b)*CH + h*HD) * HWN + n;
    float acc[HD];
#pragma unroll
    for (int i = 0; i < HD; i++) acc[i] = 0.f;

#pragma unroll 4
    for (int j = 0; j < HD; j++) {
        const float vj = __ldg(&vbase[(size_t)j * HWN]);
#pragma unroll
        for (int i = 0; i < HD; i++) acc[i] += As[i*HD + j] * vj;
    }

    float* obase = g_attnout + ((size_t)b*CH + h*HD) * HWN + n;
#pragma unroll
    for (int i = 0; i < HD; i++) obase[(size_t)i * HWN] = acc[i];
}

// ---------------- launch ----------------
extern "C" void kernel_launch(void* const* d_in, const int* in_sizes, int n_in,
                              void* d_out, int out_size)
{
    const float* x      = (const float*)d_in[0];
    const float* msg    = (const float*)d_in[1];
    const float* w_qkv  = (const float*)d_in[2];
    const float* w_dw   = (const float*)d_in[3];
    const float* w_proj = (const float*)d_in[4];
    const float* temp   = (const float*)d_in[5];
    float* out = (float*)d_out;

    // 1. q/k/v 1x1-conv GEMMs (q from message; k,v from x)
    qkv_gemm_kernel<<<dim3(HWN/128, CH/128, 3*BATCH), 256>>>(x, msg, w_qkv);
    // 2. depthwise 3x3
    dwconv_kernel<<<dim3(IMG/32, IMG/8, 3*BATCH*CH), dim3(32,8)>>>(w_dw);
    // 3. squared norms of q_m and k rows
    sqnorm_kernel<<<2*BATCH*CH, 256>>>();
    // 4. Gram partials (deterministic two-phase)
    gram_kernel<<<dim3(GRAM_CHUNKS, NBH), dim3(16,16)>>>();
    // 5. reduce partials
    gram_reduce_kernel<<<(NBH*HD*HD)/1024, 1024>>>();
    // 6. normalize + temperature + softmax
    softmax_kernel<<<NBH, 64>>>(temp);
    // 7. A @ V
    av_kernel<<<dim3(HWN/256, NBH), 256>>>();
    // 8. output projection GEMM
    proj_gemm_kernel<<<dim3(HWN/128, CH/128, BATCH), 256>>>(w_proj, out);
}

// round 5
// speedup vs baseline: 1.4275x; 1.4275x over previous
#include <cuda_runtime.h>
#include <cuda_bf16.h>
#include <math.h>
#include <stdint.h>

#define BATCH 4
#define CH    384
#define IMG   128
#define HWN   (IMG*IMG)      // 16384
#define NH    8
#define HD    48
#define NBH   (BATCH*NH)     // 32
#define GRAM_CHUNKS 32
#define NCHUNK (HWN/GRAM_CHUNKS)
#define KTOT  384

// ---------------- scratch (device globals; no allocation) ----------------
__device__ __align__(16) float g_pre  [3ull*BATCH*CH*HWN];
__device__ __align__(16) float g_post [3ull*BATCH*CH*HWN];
__device__ __align__(16) float g_sqn  [2*BATCH*CH];
__device__ __align__(16) float g_gpart[(size_t)GRAM_CHUNKS*NBH*HD*HD];
__device__ __align__(16) float g_gram [NBH*HD*HD];
// bf16 split operands
__device__ __align__(16) unsigned short g_wh  [(size_t)1536*KTOT];
__device__ __align__(16) unsigned short g_wl  [(size_t)1536*KTOT];
__device__ __align__(16) unsigned short g_inth[(size_t)2*BATCH*HWN*CH];  // [inp][b][p][c]
__device__ __align__(16) unsigned short g_intl[(size_t)2*BATCH*HWN*CH];
__device__ __align__(16) unsigned short g_avh [(size_t)BATCH*HWN*CH];    // [b][p][c]
__device__ __align__(16) unsigned short g_avl [(size_t)BATCH*HWN*CH];

// ---------------- PTX helpers (sm_80-level only; no 'a'-suffix features) ----------------
__device__ __forceinline__ uint32_t smem_u32(const void* p) {
    uint32_t a;
    asm("{ .reg .u64 t; cvta.to.shared.u64 t, %1; cvt.u32.u64 %0, t; }" : "=r"(a) : "l"(p));
    return a;
}
__device__ __forceinline__ void cpa16(uint32_t saddr, const void* gptr) {
    asm volatile("cp.async.cg.shared.global [%0], [%1], 16;" :: "r"(saddr), "l"(gptr));
}
__device__ __forceinline__ void ldm_x4(uint32_t* r, uint32_t addr) {
    asm volatile("ldmatrix.sync.aligned.m8n8.x4.shared.b16 {%0,%1,%2,%3}, [%4];"
        : "=r"(r[0]), "=r"(r[1]), "=r"(r[2]), "=r"(r[3]) : "r"(addr));
}
__device__ __forceinline__ void ldm_x2(uint32_t* r, uint32_t addr) {
    asm volatile("ldmatrix.sync.aligned.m8n8.x2.shared.b16 {%0,%1}, [%2];"
        : "=r"(r[0]), "=r"(r[1]) : "r"(addr));
}
__device__ __forceinline__ void mma_bf16(float* c, const uint32_t* a, const uint32_t* b) {
    asm volatile("mma.sync.aligned.m16n8k16.row.col.f32.bf16.bf16.f32 "
        "{%0,%1,%2,%3}, {%4,%5,%6,%7}, {%8,%9}, {%0,%1,%2,%3};"
        : "+f"(c[0]), "+f"(c[1]), "+f"(c[2]), "+f"(c[3])
        : "r"(a[0]), "r"(a[1]), "r"(a[2]), "r"(a[3]), "r"(b[0]), "r"(b[1]));
}

// ---------------- mma.sync bf16x3 GEMM: C[128 x 128] tile, K=384 ----------------
// smem: per stage 4 regions (Ah, Al, Bh, Bl), each 128 rows x 32 bf16, row stride
// 40 shorts (80 B) -> conflict-free ldmatrix. Region = 10240 B, stage = 40960 B.
#define BM 128
#define BN 128
#define BK 32
#define KITERS (KTOT/BK)       // 12
#define REGB   10240
#define STAGEB 40960
#define GEMM_SMEM (2*STAGEB)   // 81920

__device__ __forceinline__ void gemm_bf16x3(
    const unsigned short* __restrict__ Ah, const unsigned short* __restrict__ Al,
    const unsigned short* __restrict__ Bh, const unsigned short* __restrict__ Bl,
    float* __restrict__ Y)
{
    extern __shared__ char gsm[];
    const uint32_t smem_base = smem_u32(gsm);
    const int tid = threadIdx.x, wid = tid >> 5, lane = tid & 31;
    const int mBase = (wid >> 2) * 64;       // 2 warp-rows
    const int nBase = (wid & 3) * 32;        // 4 warp-cols

    const int aRow = lane & 15, aCol = lane >> 4;       // ldmatrix x4 addressing
    const int i16  = lane & 15;
    const int bRow = i16 & 7,  bCol = i16 >> 3;         // ldmatrix x2 addressing

    float acc[4][4][4];
#pragma unroll
    for (int mt = 0; mt < 4; mt++)
#pragma unroll
        for (int nt = 0; nt < 4; nt++)
#pragma unroll
            for (int q = 0; q < 4; q++) acc[mt][nt][q] = 0.f;

    // stage loader: 2048 x 16B chunks (A hi/lo + B hi/lo), 8 per thread
    auto load_stage = [&](int st, int k0) {
        const uint32_t sb = smem_base + (st & 1) * STAGEB;
#pragma unroll
        for (int j = 0; j < 8; j++) {
            const int idx = tid + 256 * j;
            const int region = idx >> 9;             // 0..3
            const int rem = idx & 511;
            const int r = rem >> 2, c = rem & 3;
            const uint32_t saddr = sb + region * REGB + r * 80 + c * 16;
            const unsigned short* gsrc;
            if      (region == 0) gsrc = Ah + (size_t)r * KTOT + k0 + c * 8;
            else if (region == 1) gsrc = Al + (size_t)r * KTOT + k0 + c * 8;
            else if (region == 2) gsrc = Bh + (size_t)r * KTOT + k0 + c * 8;
            else                  gsrc = Bl + (size_t)r * KTOT + k0 + c * 8;
            cpa16(saddr, gsrc);
        }
        asm volatile("cp.async.commit_group;" ::: "memory");
    };

    load_stage(0, 0);

    for (int it = 0; it < KITERS; it++) {
        if (it + 1 < KITERS) {
            load_stage(it + 1, (it + 1) * BK);
            asm volatile("cp.async.wait_group 1;" ::: "memory");
        } else {
            asm volatile("cp.async.wait_group 0;" ::: "memory");
        }
        __syncthreads();

        const uint32_t sb  = smem_base + (it & 1) * STAGEB;
        const uint32_t sAh = sb, sAl = sb + REGB, sBh = sb + 2*REGB, sBl = sb + 3*REGB;

#pragma unroll
        for (int ks = 0; ks < 2; ks++) {
            const uint32_t akb = ks * 32 + aCol * 16;     // byte offset in row
            const uint32_t bkb = ks * 32 + bCol * 16;
            uint32_t fAh[4][4], fAl[4][4], fBh[4][2], fBl[4][2];
#pragma unroll
            for (int mt = 0; mt < 4; mt++)
                ldm_x4(fAh[mt], sAh + (uint32_t)(mBase + mt*16 + aRow) * 80 + akb);
#pragma unroll
            for (int nt = 0; nt < 4; nt++)
                ldm_x2(fBh[nt], sBh + (uint32_t)(nBase + nt*8 + bRow) * 80 + bkb);
#pragma unroll
            for (int mt = 0; mt < 4; mt++)
#pragma unroll
                for (int nt = 0; nt < 4; nt++) mma_bf16(acc[mt][nt], fAh[mt], fBh[nt]);
#pragma unroll
            for (int nt = 0; nt < 4; nt++)
                ldm_x2(fBl[nt], sBl + (uint32_t)(nBase + nt*8 + bRow) * 80 + bkb);
#pragma unroll
            for (int mt = 0; mt < 4; mt++)
#pragma unroll
                for (int nt = 0; nt < 4; nt++) mma_bf16(acc[mt][nt], fAh[mt], fBl[nt]);
#pragma unroll
            for (int mt = 0; mt < 4; mt++)
                ldm_x4(fAl[mt], sAl + (uint32_t)(mBase + mt*16 + aRow) * 80 + akb);
#pragma unroll
            for (int mt = 0; mt < 4; mt++)
#pragma unroll
                for (int nt = 0; nt < 4; nt++) mma_bf16(acc[mt][nt], fAl[mt], fBh[nt]);
        }
        __syncthreads();
    }

    // epilogue: direct stores (float2 per fragment row)
    const int gr = lane >> 2, gc = (lane & 3) * 2;
#pragma unroll
    for (int mt = 0; mt < 4; mt++) {
#pragma unroll
        for (int nt = 0; nt < 4; nt++) {
            float* d0 = Y + (size_t)(mBase + mt*16 + gr) * HWN + nBase + nt*8 + gc;
            d0[0] = acc[mt][nt][0]; d0[1] = acc[mt][nt][1];
            float* d1 = d0 + 8 * HWN;
            d1[0] = acc[mt][nt][2]; d1[1] = acc[mt][nt][3];
        }
    }
}

__global__ __launch_bounds__(256, 1)
void qkv_gemm_tc()
{
    const int z = blockIdx.z, s = z >> 2, b = z & 3;
    const int row0 = blockIdx.y * BM, n0 = blockIdx.x * BN;
    const size_t aoff = (size_t)(s * CH + row0) * KTOT;
    const int inp = (s == 0) ? 1 : 0;   // q comes from message
    const size_t boff = ((size_t)(inp * BATCH + b) * HWN + n0) * KTOT;
    float* Y = g_pre + ((size_t)z * CH + row0) * HWN + n0;
    gemm_bf16x3(g_wh + aoff, g_wl + aoff, g_inth + boff, g_intl + boff, Y);
}

__global__ __launch_bounds__(256, 1)
void proj_gemm_tc(float* __restrict__ out)
{
    const int b = blockIdx.z;
    const int row0 = blockIdx.y * BM, n0 = blockIdx.x * BN;
    const size_t aoff = (size_t)(1152 + row0) * KTOT;
    const size_t boff = ((size_t)b * HWN + n0) * KTOT;
    float* Y = out + ((size_t)b * CH + row0) * HWN + n0;
    gemm_bf16x3(g_wh + aoff, g_wl + aoff, g_avh + boff, g_avl + boff, Y);
}

// ---------------- convert weights to bf16 hi/lo ----------------
__global__ __launch_bounds__(256) void wconv_kernel(const float* __restrict__ wqkv,
                                                    const float* __restrict__ wproj)
{
    const size_t i = (size_t)blockIdx.x * 256 + threadIdx.x;   // < 1536*384
    const float f = (i < (size_t)1152 * KTOT) ? wqkv[i] : wproj[i - (size_t)1152 * KTOT];
    const uint32_t bits = __float_as_uint(f);
    const float hi = __uint_as_float(bits & 0xFFFF0000u);
    const __nv_bfloat16 lo = __float2bfloat16(f - hi);
    g_wh[i] = (unsigned short)(bits >> 16);
    g_wl[i] = *(const unsigned short*)&lo;
}

// ---------------- transpose + convert inputs: [b][c][p] -> [inp][b][p][c] hi/lo ----------------
__global__ __launch_bounds__(256) void trx_kernel(const float* __restrict__ x,
                                                  const float* __restrict__ msg)
{
    __shared__ float t[32][33];
    const int z = blockIdx.z, inp = z >> 2, b = z & 3;
    const int p0 = blockIdx.x * 32, c0 = blockIdx.y * 32;
    const int tx = threadIdx.x, ty = threadIdx.y;
    const float* src = (inp ? msg : x) + ((size_t)b * CH + c0) * HWN + p0;
    for (int yy = ty; yy < 32; yy += 8) t[yy][tx] = src[(size_t)yy * HWN + tx];
    __syncthreads();
    unsigned short* dh = g_inth + ((size_t)z * HWN + p0) * CH + c0;
    unsigned short* dl = g_intl + ((size_t)z * HWN + p0) * CH + c0;
    for (int yy = ty; yy < 32; yy += 8) {
        const float f = t[tx][yy];
        const uint32_t bits = __float_as_uint(f);
        const float hi = __uint_as_float(bits & 0xFFFF0000u);
        const __nv_bfloat16 lo = __float2bfloat16(f - hi);
        dh[(size_t)yy * CH + tx] = (unsigned short)(bits >> 16);
        dl[(size_t)yy * CH + tx] = *(const unsigned short*)&lo;
    }
}

// ---------------- depthwise 3x3, SAME ----------------
__global__ __launch_bounds__(256)
void dwconv_kernel(const float* __restrict__ wdw)
{
    const int zc = blockIdx.z;
    const int z  = zc / CH;
    const int c  = zc % CH;
    const int s  = z / BATCH;
    const float* wk = wdw + (size_t)(s*CH + c) * 9;
    const float* in   = g_pre  + (size_t)zc * HWN;
    float*       outp = g_post + (size_t)zc * HWN;

    float w[9];
#pragma unroll
    for (int i = 0; i < 9; i++) w[i] = wk[i];

    const int px = blockIdx.x * 32 + threadIdx.x;
    const int py = blockIdx.y * 8  + threadIdx.y;
    float acc = 0.f;
#pragma unroll
    for (int ky = 0; ky < 3; ky++) {
        const int iy = py + ky - 1;
        if (iy < 0 || iy >= IMG) continue;
#pragma unroll
        for (int kx = 0; kx < 3; kx++) {
            const int ix = px + kx - 1;
            if (ix < 0 || ix >= IMG) continue;
            acc += __ldg(&in[iy*IMG + ix]) * w[ky*3 + kx];
        }
    }
    outp[py*IMG + px] = acc;
}

// ---------------- squared norms ----------------
__global__ __launch_bounds__(256)
void sqnorm_kernel()
{
    const int r = blockIdx.x;
    const float* p = g_post + (size_t)r * HWN;
    const int tid = threadIdx.x;
    float s = 0.f;
    for (int i = tid*4; i < HWN; i += 256*4) {
        float4 v = *(const float4*)&p[i];
        s += v.x*v.x + v.y*v.y + v.z*v.z + v.w*v.w;
    }
    __shared__ float red[8];
#pragma unroll
    for (int o = 16; o > 0; o >>= 1) s += __shfl_xor_sync(0xffffffffu, s, o);
    if ((tid & 31) == 0) red[tid >> 5] = s;
    __syncthreads();
    if (tid == 0) {
        float t = 0.f;
#pragma unroll
        for (int i = 0; i < 8; i++) t += red[i];
        g_sqn[r] = t;
    }
}

// ---------------- Gram partials ----------------
__global__ __launch_bounds__(256)
void gram_kernel()
{
    __shared__ __align__(16) float qs[48][65];
    __shared__ __align__(16) float ks[48][65];

    const int bh = blockIdx.y;
    const int b  = bh >> 3;
    const int h  = bh & 7;
    const int n0 = blockIdx.x * NCHUNK;
    const float* qbase = g_post + ((size_t)(0*BATCH + b)*CH + h*HD) * HWN;
    const float* kbase = g_post + ((size_t)(1*BATCH + b)*CH + h*HD) * HWN;
    const int tid = threadIdx.y * 16 + threadIdx.x;

    float acc[3][3];
#pragma unroll
    for (int r = 0; r < 3; r++)
#pragma unroll
        for (int c = 0; c < 3; c++) acc[r][c] = 0.f;

    const int i0 = threadIdx.y * 3;
    const int j0 = threadIdx.x * 3;

    for (int t = 0; t < NCHUNK; t += 64) {
        for (int e = tid; e < 48*64; e += 256) {
            const int i = e >> 6, j = e & 63;
            qs[i][j] = qbase[(size_t)i*HWN + n0 + t + j];
            ks[i][j] = kbase[(size_t)i*HWN + n0 + t + j];
        }
        __syncthreads();
#pragma unroll 8
        for (int nn = 0; nn < 64; nn++) {
            const float q0 = qs[i0+0][nn], q1 = qs[i0+1][nn], q2 = qs[i0+2][nn];
            const float k0 = ks[j0+0][nn], k1 = ks[j0+1][nn], k2 = ks[j0+2][nn];
            acc[0][0] += q0*k0; acc[0][1] += q0*k1; acc[0][2] += q0*k2;
            acc[1][0] += q1*k0; acc[1][1] += q1*k1; acc[1][2] += q1*k2;
            acc[2][0] += q2*k0; acc[2][1] += q2*k1; acc[2][2] += q2*k2;
        }
        __syncthreads();
    }

    float* gp = g_gpart + ((size_t)blockIdx.x * NBH + bh) * (HD*HD);
#pragma unroll
    for (int r = 0; r < 3; r++)
#pragma unroll
        for (int c = 0; c < 3; c++)
            gp[(i0+r)*HD + (j0+c)] = acc[r][c];
}

__global__ __launch_bounds__(1024)
void gram_reduce_kernel()
{
    const int idx = blockIdx.x * 1024 + threadIdx.x;
    float s = 0.f;
#pragma unroll
    for (int ch = 0; ch < GRAM_CHUNKS; ch++)
        s += g_gpart[(size_t)ch * NBH * (HD*HD) + idx];
    g_gram[idx] = s;
}

// ---------------- normalize + temperature + softmax ----------------
__global__ __launch_bounds__(64)
void softmax_kernel(const float* __restrict__ temp)
{
    const int bh = blockIdx.x;
    const int b  = bh >> 3;
    const int h  = bh & 7;
    const int i  = threadIdx.x;
    if (i >= HD) return;

    float* gg = g_gram + (size_t)bh * (HD*HD) + i*HD;
    const float invq = rsqrtf(fmaxf(g_sqn[b*CH + h*HD + i], 1e-24f));
    const float T = temp[h];

    float row[HD];
    float m = -3.4e38f;
#pragma unroll
    for (int j = 0; j < HD; j++) {
        const float invk = rsqrtf(fmaxf(g_sqn[(BATCH + b)*CH + h*HD + j], 1e-24f));
        const float v = gg[j] * invq * invk * T;
        row[j] = v;
        m = fmaxf(m, v);
    }
    float sum = 0.f;
#pragma unroll
    for (int j = 0; j < HD; j++) { row[j] = expf(row[j] - m); sum += row[j]; }
    const float inv = 1.f / sum;
#pragma unroll
    for (int j = 0; j < HD; j++) gg[j] = row[j] * inv;
}

// ---------------- A@V, writing bf16 hi/lo transposed [b][p][c] ----------------
__global__ __launch_bounds__(256)
void av_kernel()
{
    __shared__ __align__(16) float As[HD*HD];
    const int bh = blockIdx.y;
    const int b  = bh >> 3;
    const int h  = bh & 7;
    const int tid = threadIdx.x;
    const int n = blockIdx.x * 256 + tid;

    for (int e = tid; e < HD*HD; e += 256) As[e] = g_gram[(size_t)bh * (HD*HD) + e];
    __syncthreads();

    const float* vbase = g_post + ((size_t)(2*BATCH + b)*CH + h*HD) * HWN + n;
    float acc[HD];
#pragma unroll
    for (int i = 0; i < HD; i++) acc[i] = 0.f;

#pragma unroll 4
    for (int j = 0; j < HD; j++) {
        const float vj = __ldg(&vbase[(size_t)j * HWN]);
#pragma unroll
        for (int i = 0; i < HD; i++) acc[i] += As[i*HD + j] * vj;
    }

    unsigned short* dh = g_avh + ((size_t)b * HWN + n) * CH + h*HD;
    unsigned short* dl = g_avl + ((size_t)b * HWN + n) * CH + h*HD;
#pragma unroll
    for (int i = 0; i < HD; i++) {
        const uint32_t bits = __float_as_uint(acc[i]);
        const float hi = __uint_as_float(bits & 0xFFFF0000u);
        const __nv_bfloat16 lo = __float2bfloat16(acc[i] - hi);
        dh[i] = (unsigned short)(bits >> 16);
        dl[i] = *(const unsigned short*)&lo;
    }
}

// ---------------- launch ----------------
extern "C" void kernel_launch(void* const* d_in, const int* in_sizes, int n_in,
                              void* d_out, int out_size)
{
    const float* x      = (const float*)d_in[0];
    const float* msg    = (const float*)d_in[1];
    const float* w_qkv  = (const float*)d_in[2];
    const float* w_dw   = (const float*)d_in[3];
    const float* w_proj = (const float*)d_in[4];
    const float* temp   = (const float*)d_in[5];
    float* out = (float*)d_out;

    cudaFuncSetAttribute(qkv_gemm_tc, cudaFuncAttributeMaxDynamicSharedMemorySize, GEMM_SMEM);
    cudaFuncSetAttribute(proj_gemm_tc, cudaFuncAttributeMaxDynamicSharedMemorySize, GEMM_SMEM);

    // 0. bf16 hi/lo conversions
    wconv_kernel<<<(1536*KTOT)/256, 256>>>(w_qkv, w_proj);
    trx_kernel<<<dim3(HWN/32, CH/32, 2*BATCH), dim3(32,8)>>>(x, msg);
    // 1. qkv GEMMs on tensor cores (mma.sync bf16x3 split)
    qkv_gemm_tc<<<dim3(HWN/BN, CH/BM, 3*BATCH), 256, GEMM_SMEM>>>();
    // 2. depthwise 3x3
    dwconv_kernel<<<dim3(IMG/32, IMG/8, 3*BATCH*CH), dim3(32,8)>>>(w_dw);
    // 3. squared norms
    sqnorm_kernel<<<2*BATCH*CH, 256>>>();
    // 4-5. Gram (two-phase deterministic)
    gram_kernel<<<dim3(GRAM_CHUNKS, NBH), dim3(16,16)>>>();
    gram_reduce_kernel<<<(NBH*HD*HD)/1024, 1024>>>();
    // 6. softmax
    softmax_kernel<<<NBH, 64>>>(temp);
    // 7. A@V (emits bf16 hi/lo, transposed)
    av_kernel<<<dim3(HWN/256, NBH), 256>>>();
    // 8. output projection on tensor cores
    proj_gemm_tc<<<dim3(HWN/BN, CH/BM, BATCH), 256, GEMM_SMEM>>>(out);
}

// round 7
// speedup vs baseline: 1.6755x; 1.1737x over previous
#include <cuda_runtime.h>
#include <cuda_bf16.h>
#include <math.h>
#include <stdint.h>

#define BATCH 4
#define CH    384
#define IMG   128
#define HWN   (IMG*IMG)      // 16384
#define NH    8
#define HD    48
#define NBH   (BATCH*NH)     // 32
#define GRAM_CHUNKS 32
#define NCHUNK (HWN/GRAM_CHUNKS)
#define KTOT  384

// ---------------- scratch (device globals; no allocation) ----------------
__device__ __align__(16) float g_pre  [3ull*BATCH*CH*HWN];
__device__ __align__(16) float g_post [3ull*BATCH*CH*HWN];
__device__ __align__(16) float g_snp  [2*BATCH*CH*16];      // per-block sqnorm partials
__device__ __align__(16) float g_sqn  [2*BATCH*CH];
__device__ __align__(16) float g_gpart[(size_t)GRAM_CHUNKS*NBH*HD*HD];
__device__ __align__(16) float g_gram [NBH*HD*HD];
// bf16 split operands
__device__ __align__(16) unsigned short g_wh  [(size_t)1536*KTOT];
__device__ __align__(16) unsigned short g_wl  [(size_t)1536*KTOT];
__device__ __align__(16) unsigned short g_inth[(size_t)2*BATCH*HWN*CH];  // [inp][b][p][c]
__device__ __align__(16) unsigned short g_intl[(size_t)2*BATCH*HWN*CH];
__device__ __align__(16) unsigned short g_avh [(size_t)BATCH*HWN*CH];    // [b][p][c]
__device__ __align__(16) unsigned short g_avl [(size_t)BATCH*HWN*CH];

// ---------------- PTX helpers (sm_80-level only) ----------------
__device__ __forceinline__ uint32_t smem_u32(const void* p) {
    uint32_t a;
    asm("{ .reg .u64 t; cvta.to.shared.u64 t, %1; cvt.u32.u64 %0, t; }" : "=r"(a) : "l"(p));
    return a;
}
__device__ __forceinline__ void cpa16(uint32_t saddr, const void* gptr) {
    asm volatile("cp.async.cg.shared.global [%0], [%1], 16;" :: "r"(saddr), "l"(gptr));
}
__device__ __forceinline__ void ldm_x4(uint32_t* r, uint32_t addr) {
    asm volatile("ldmatrix.sync.aligned.m8n8.x4.shared.b16 {%0,%1,%2,%3}, [%4];"
        : "=r"(r[0]), "=r"(r[1]), "=r"(r[2]), "=r"(r[3]) : "r"(addr));
}
__device__ __forceinline__ void ldm_x2(uint32_t* r, uint32_t addr) {
    asm volatile("ldmatrix.sync.aligned.m8n8.x2.shared.b16 {%0,%1}, [%2];"
        : "=r"(r[0]), "=r"(r[1]) : "r"(addr));
}
__device__ __forceinline__ void mma_bf16(float* c, const uint32_t* a, const uint32_t* b) {
    asm volatile("mma.sync.aligned.m16n8k16.row.col.f32.bf16.bf16.f32 "
        "{%0,%1,%2,%3}, {%4,%5,%6,%7}, {%8,%9}, {%0,%1,%2,%3};"
        : "+f"(c[0]), "+f"(c[1]), "+f"(c[2]), "+f"(c[3])
        : "r"(a[0]), "r"(a[1]), "r"(a[2]), "r"(a[3]), "r"(b[0]), "r"(b[1]));
}

// ---------------- mma.sync bf16x3 GEMM: C[128 x 128] tile, K=384 ----------------
#define BM 128
#define BN 128
#define BK 32
#define KITERS (KTOT/BK)       // 12
#define REGB   10240
#define STAGEB 40960
#define GEMM_SMEM (2*STAGEB)   // 81920

__device__ __forceinline__ void gemm_bf16x3(
    const unsigned short* __restrict__ Ah, const unsigned short* __restrict__ Al,
    const unsigned short* __restrict__ Bh, const unsigned short* __restrict__ Bl,
    float* __restrict__ Y)
{
    extern __shared__ char gsm[];
    const uint32_t smem_base = smem_u32(gsm);
    const int tid = threadIdx.x, wid = tid >> 5, lane = tid & 31;
    const int mBase = (wid >> 2) * 64;       // 2 warp-rows
    const int nBase = (wid & 3) * 32;        // 4 warp-cols

    const int aRow = lane & 15, aCol = lane >> 4;
    const int i16  = lane & 15;
    const int bRow = i16 & 7,  bCol = i16 >> 3;

    float acc[4][4][4];
#pragma unroll
    for (int mt = 0; mt < 4; mt++)
#pragma unroll
        for (int nt = 0; nt < 4; nt++)
#pragma unroll
            for (int q = 0; q < 4; q++) acc[mt][nt][q] = 0.f;

    auto load_stage = [&](int st, int k0) {
        const uint32_t sb = smem_base + (st & 1) * STAGEB;
#pragma unroll
        for (int j = 0; j < 8; j++) {
            const int idx = tid + 256 * j;
            const int region = idx >> 9;
            const int rem = idx & 511;
            const int r = rem >> 2, c = rem & 3;
            const uint32_t saddr = sb + region * REGB + r * 80 + c * 16;
            const unsigned short* gsrc;
            if      (region == 0) gsrc = Ah + (size_t)r * KTOT + k0 + c * 8;
            else if (region == 1) gsrc = Al + (size_t)r * KTOT + k0 + c * 8;
            else if (region == 2) gsrc = Bh + (size_t)r * KTOT + k0 + c * 8;
            else                  gsrc = Bl + (size_t)r * KTOT + k0 + c * 8;
            cpa16(saddr, gsrc);
        }
        asm volatile("cp.async.commit_group;" ::: "memory");
    };

    load_stage(0, 0);

    for (int it = 0; it < KITERS; it++) {
        if (it + 1 < KITERS) {
            load_stage(it + 1, (it + 1) * BK);
            asm volatile("cp.async.wait_group 1;" ::: "memory");
        } else {
            asm volatile("cp.async.wait_group 0;" ::: "memory");
        }
        __syncthreads();

        const uint32_t sb  = smem_base + (it & 1) * STAGEB;
        const uint32_t sAh = sb, sAl = sb + REGB, sBh = sb + 2*REGB, sBl = sb + 3*REGB;

#pragma unroll
        for (int ks = 0; ks < 2; ks++) {
            const uint32_t akb = ks * 32 + aCol * 16;
            const uint32_t bkb = ks * 32 + bCol * 16;
            uint32_t fAh[4][4], fAl[4][4], fBh[4][2], fBl[4][2];
#pragma unroll
            for (int mt = 0; mt < 4; mt++)
                ldm_x4(fAh[mt], sAh + (uint32_t)(mBase + mt*16 + aRow) * 80 + akb);
#pragma unroll
            for (int nt = 0; nt < 4; nt++)
                ldm_x2(fBh[nt], sBh + (uint32_t)(nBase + nt*8 + bRow) * 80 + bkb);
#pragma unroll
            for (int mt = 0; mt < 4; mt++)
#pragma unroll
                for (int nt = 0; nt < 4; nt++) mma_bf16(acc[mt][nt], fAh[mt], fBh[nt]);
#pragma unroll
            for (int nt = 0; nt < 4; nt++)
                ldm_x2(fBl[nt], sBl + (uint32_t)(nBase + nt*8 + bRow) * 80 + bkb);
#pragma unroll
            for (int mt = 0; mt < 4; mt++)
#pragma unroll
                for (int nt = 0; nt < 4; nt++) mma_bf16(acc[mt][nt], fAh[mt], fBl[nt]);
#pragma unroll
            for (int mt = 0; mt < 4; mt++)
                ldm_x4(fAl[mt], sAl + (uint32_t)(mBase + mt*16 + aRow) * 80 + akb);
#pragma unroll
            for (int mt = 0; mt < 4; mt++)
#pragma unroll
                for (int nt = 0; nt < 4; nt++) mma_bf16(acc[mt][nt], fAl[mt], fBh[nt]);
        }
        __syncthreads();
    }

    const int gr = lane >> 2, gc = (lane & 3) * 2;
#pragma unroll
    for (int mt = 0; mt < 4; mt++) {
#pragma unroll
        for (int nt = 0; nt < 4; nt++) {
            float* d0 = Y + (size_t)(mBase + mt*16 + gr) * HWN + nBase + nt*8 + gc;
            d0[0] = acc[mt][nt][0]; d0[1] = acc[mt][nt][1];
            float* d1 = d0 + 8 * HWN;
            d1[0] = acc[mt][nt][2]; d1[1] = acc[mt][nt][3];
        }
    }
}

__global__ __launch_bounds__(256, 1)
void qkv_gemm_tc()
{
    const int z = blockIdx.z, s = z >> 2, b = z & 3;
    const int row0 = blockIdx.y * BM, n0 = blockIdx.x * BN;
    const size_t aoff = (size_t)(s * CH + row0) * KTOT;
    const int inp = (s == 0) ? 1 : 0;   // q comes from message
    const size_t boff = ((size_t)(inp * BATCH + b) * HWN + n0) * KTOT;
    float* Y = g_pre + ((size_t)z * CH + row0) * HWN + n0;
    gemm_bf16x3(g_wh + aoff, g_wl + aoff, g_inth + boff, g_intl + boff, Y);
}

__global__ __launch_bounds__(256, 1)
void proj_gemm_tc(float* __restrict__ out)
{
    const int b = blockIdx.z;
    const int row0 = blockIdx.y * BM, n0 = blockIdx.x * BN;
    const size_t aoff = (size_t)(1152 + row0) * KTOT;
    const size_t boff = ((size_t)b * HWN + n0) * KTOT;
    float* Y = out + ((size_t)b * CH + row0) * HWN + n0;
    gemm_bf16x3(g_wh + aoff, g_wl + aoff, g_avh + boff, g_avl + boff, Y);
}

// ---------------- convert weights to bf16 hi/lo ----------------
__global__ __launch_bounds__(256) void wconv_kernel(const float* __restrict__ wqkv,
                                                    const float* __restrict__ wproj)
{
    const size_t i = (size_t)blockIdx.x * 256 + threadIdx.x;
    const float f = (i < (size_t)1152 * KTOT) ? wqkv[i] : wproj[i - (size_t)1152 * KTOT];
    const uint32_t bits = __float_as_uint(f);
    const float hi = __uint_as_float(bits & 0xFFFF0000u);
    const __nv_bfloat16 lo = __float2bfloat16(f - hi);
    g_wh[i] = (unsigned short)(bits >> 16);
    g_wl[i] = *(const unsigned short*)&lo;
}

// ---------------- transpose + convert inputs ----------------
__global__ __launch_bounds__(256) void trx_kernel(const float* __restrict__ x,
                                                  const float* __restrict__ msg)
{
    __shared__ float t[32][33];
    const int z = blockIdx.z, inp = z >> 2, b = z & 3;
    const int p0 = blockIdx.x * 32, c0 = blockIdx.y * 32;
    const int tx = threadIdx.x, ty = threadIdx.y;
    const float* src = (inp ? msg : x) + ((size_t)b * CH + c0) * HWN + p0;
    for (int yy = ty; yy < 32; yy += 8) t[yy][tx] = src[(size_t)yy * HWN + tx];
    __syncthreads();
    unsigned short* dh = g_inth + ((size_t)z * HWN + p0) * CH + c0;
    unsigned short* dl = g_intl + ((size_t)z * HWN + p0) * CH + c0;
    for (int yy = ty; yy < 32; yy += 8) {
        const float f = t[tx][yy];
        const uint32_t bits = __float_as_uint(f);
        const float hi = __uint_as_float(bits & 0xFFFF0000u);
        const __nv_bfloat16 lo = __float2bfloat16(f - hi);
        dh[(size_t)yy * CH + tx] = (unsigned short)(bits >> 16);
        dl[(size_t)yy * CH + tx] = *(const unsigned short*)&lo;
    }
}

// ---------------- depthwise 3x3: 4 px/thread + fused sqnorm partials ----------------
__global__ __launch_bounds__(256)
void dwconv_kernel(const float* __restrict__ wdw)
{
    __shared__ float red[8];

    const int zc = blockIdx.z;            // z*CH + c, z in [0,12)
    const int z  = zc / CH;
    const int c  = zc % CH;
    const int s  = z / BATCH;
    const float* wk = wdw + (size_t)(s*CH + c) * 9;
    const float* in   = g_pre  + (size_t)zc * HWN;
    float*       outp = g_post + (size_t)zc * HWN;

    float w[9];
#pragma unroll
    for (int i = 0; i < 9; i++) w[i] = __ldg(&wk[i]);

    const int tx = threadIdx.x;           // 0..31
    const int ty = threadIdx.y;           // 0..7
    const int px0 = tx * 4;
    const int py  = blockIdx.y * 8 + ty;

    float r[3][6];
#pragma unroll
    for (int ky = 0; ky < 3; ky++) {
        const int iy = py + ky - 1;
        if (iy < 0 || iy >= IMG) {
#pragma unroll
            for (int e = 0; e < 6; e++) r[ky][e] = 0.f;
        } else {
            const float* base = in + (size_t)iy * IMG + px0;
            const float4 v = *(const float4*)base;
            r[ky][1] = v.x; r[ky][2] = v.y; r[ky][3] = v.z; r[ky][4] = v.w;
            r[ky][0] = (px0 > 0)       ? __ldg(base - 1) : 0.f;
            r[ky][5] = (px0 + 4 < IMG) ? __ldg(base + 4) : 0.f;
        }
    }

    float a0 = 0.f, a1 = 0.f, a2 = 0.f, a3 = 0.f;
#pragma unroll
    for (int ky = 0; ky < 3; ky++) {
#pragma unroll
        for (int kx = 0; kx < 3; kx++) {
            const float wv = w[ky*3 + kx];
            a0 += r[ky][0 + kx] * wv;
            a1 += r[ky][1 + kx] * wv;
            a2 += r[ky][2 + kx] * wv;
            a3 += r[ky][3 + kx] * wv;
        }
    }
    *(float4*)(outp + (size_t)py * IMG + px0) = make_float4(a0, a1, a2, a3);

    // sqnorm partial (reduction unconditional; only the store is predicated)
    float loc = a0*a0 + a1*a1 + a2*a2 + a3*a3;
    const int tid = ty * 32 + tx;
#pragma unroll
    for (int o = 16; o > 0; o >>= 1) loc += __shfl_xor_sync(0xffffffffu, loc, o);
    if ((tid & 31) == 0) red[tid >> 5] = loc;
    __syncthreads();
    if (tid == 0 && s < 2) {
        float t = 0.f;
#pragma unroll
        for (int i = 0; i < 8; i++) t += red[i];
        g_snp[(size_t)zc * 16 + blockIdx.y] = t;
    }
}

// ---------------- reduce sqnorm partials ----------------
__global__ __launch_bounds__(256)
void sqnorm_kernel()
{
    const int r = blockIdx.x * 256 + threadIdx.x;   // < 3072
    if (r >= 2*BATCH*CH) return;
    float s = 0.f;
#pragma unroll
    for (int i = 0; i < 16; i++) s += g_snp[(size_t)r * 16 + i];
    g_sqn[r] = s;
}

// ---------------- Gram partials ----------------
__global__ __launch_bounds__(256)
void gram_kernel()
{
    __shared__ __align__(16) float qs[48][65];
    __shared__ __align__(16) float ks[48][65];

    const int bh = blockIdx.y;
    const int b  = bh >> 3;
    const int h  = bh & 7;
    const int n0 = blockIdx.x * NCHUNK;
    const float* qbase = g_post + ((size_t)(0*BATCH + b)*CH + h*HD) * HWN;
    const float* kbase = g_post + ((size_t)(1*BATCH + b)*CH + h*HD) * HWN;
    const int tid = threadIdx.y * 16 + threadIdx.x;

    float acc[3][3];
#pragma unroll
    for (int r = 0; r < 3; r++)
#pragma unroll
        for (int c = 0; c < 3; c++) acc[r][c] = 0.f;

    const int i0 = threadIdx.y * 3;
    const int j0 = threadIdx.x * 3;

    for (int t = 0; t < NCHUNK; t += 64) {
        for (int e = tid; e < 48*64; e += 256) {
            const int i = e >> 6, j = e & 63;
            qs[i][j] = qbase[(size_t)i*HWN + n0 + t + j];
            ks[i][j] = kbase[(size_t)i*HWN + n0 + t + j];
        }
        __syncthreads();
#pragma unroll 8
        for (int nn = 0; nn < 64; nn++) {
            const float q0 = qs[i0+0][nn], q1 = qs[i0+1][nn], q2 = qs[i0+2][nn];
            const float k0 = ks[j0+0][nn], k1 = ks[j0+1][nn], k2 = ks[j0+2][nn];
            acc[0][0] += q0*k0; acc[0][1] += q0*k1; acc[0][2] += q0*k2;
            acc[1][0] += q1*k0; acc[1][1] += q1*k1; acc[1][2] += q1*k2;
            acc[2][0] += q2*k0; acc[2][1] += q2*k1; acc[2][2] += q2*k2;
        }
        __syncthreads();
    }

    float* gp = g_gpart + ((size_t)blockIdx.x * NBH + bh) * (HD*HD);
#pragma unroll
    for (int r = 0; r < 3; r++)
#pragma unroll
        for (int c = 0; c < 3; c++)
            gp[(i0+r)*HD + (j0+c)] = acc[r][c];
}

__global__ __launch_bounds__(1024)
void gram_reduce_kernel()
{
    const int idx = blockIdx.x * 1024 + threadIdx.x;
    float s = 0.f;
#pragma unroll
    for (int ch = 0; ch < GRAM_CHUNKS; ch++)
        s += g_gpart[(size_t)ch * NBH * (HD*HD) + idx];
    g_gram[idx] = s;
}

// ---------------- normalize + temperature + softmax ----------------
__global__ __launch_bounds__(64)
void softmax_kernel(const float* __restrict__ temp)
{
    const int bh = blockIdx.x;
    const int b  = bh >> 3;
    const int h  = bh & 7;
    const int i  = threadIdx.x;
    if (i >= HD) return;

    float* gg = g_gram + (size_t)bh * (HD*HD) + i*HD;
    const float invq = rsqrtf(fmaxf(g_sqn[b*CH + h*HD + i], 1e-24f));
    const float T = temp[h];

    float row[HD];
    float m = -3.4e38f;
#pragma unroll
    for (int j = 0; j < HD; j++) {
        const float invk = rsqrtf(fmaxf(g_sqn[(BATCH + b)*CH + h*HD + j], 1e-24f));
        const float v = gg[j] * invq * invk * T;
        row[j] = v;
        m = fmaxf(m, v);
    }
    float sum = 0.f;
#pragma unroll
    for (int j = 0; j < HD; j++) { row[j] = expf(row[j] - m); sum += row[j]; }
    const float inv = 1.f / sum;
#pragma unroll
    for (int j = 0; j < HD; j++) gg[j] = row[j] * inv;
}

// ---------------- A@V, writing bf16 hi/lo transposed [b][p][c] ----------------
__global__ __launch_bounds__(256)
void av_kernel()
{
    __shared__ __align__(16) float As[HD*HD];
    const int bh = blockIdx.y;
    const int b  = bh >> 3;
    const int h  = bh & 7;
    const int tid = threadIdx.x;
    const int n = blockIdx.x * 256 + tid;

    for (int e = tid; e < HD*HD; e += 256) As[e] = g_gram[(size_t)bh * (HD*HD) + e];
    __syncthreads();

    const float* vbase = g_post + ((size_t)(2*BATCH + b)*CH + h*HD) * HWN + n;
    float acc[HD];
#pragma unroll
    for (int i = 0; i < HD; i++) acc[i] = 0.f;

#pragma unroll 4
    for (int j = 0; j < HD; j++) {
        const float vj = __ldg(&vbase[(size_t)j * HWN]);
#pragma unroll
        for (int i = 0; i < HD; i++) acc[i] += As[i*HD + j] * vj;
    }

    unsigned short* dh = g_avh + ((size_t)b * HWN + n) * CH + h*HD;
    unsigned short* dl = g_avl + ((size_t)b * HWN + n) * CH + h*HD;
#pragma unroll
    for (int i = 0; i < HD; i++) {
        const uint32_t bits = __float_as_uint(acc[i]);
        const float hi = __uint_as_float(bits & 0xFFFF0000u);
        const __nv_bfloat16 lo = __float2bfloat16(acc[i] - hi);
        dh[i] = (unsigned short)(bits >> 16);
        dl[i] = *(const unsigned short*)&lo;
    }
}

// ---------------- launch ----------------
extern "C" void kernel_launch(void* const* d_in, const int* in_sizes, int n_in,
                              void* d_out, int out_size)
{
    const float* x      = (const float*)d_in[0];
    const float* msg    = (const float*)d_in[1];
    const float* w_qkv  = (const float*)d_in[2];
    const float* w_dw   = (const float*)d_in[3];
    const float* w_proj = (const float*)d_in[4];
    const float* temp   = (const float*)d_in[5];
    float* out = (float*)d_out;

    cudaFuncSetAttribute(qkv_gemm_tc, cudaFuncAttributeMaxDynamicSharedMemorySize, GEMM_SMEM);
    cudaFuncSetAttribute(proj_gemm_tc, cudaFuncAttributeMaxDynamicSharedMemorySize, GEMM_SMEM);

    // 0. bf16 hi/lo conversions
    wconv_kernel<<<(1536*KTOT)/256, 256>>>(w_qkv, w_proj);
    trx_kernel<<<dim3(HWN/32, CH/32, 2*BATCH), dim3(32,8)>>>(x, msg);
    // 1. qkv GEMMs on tensor cores (mma.sync bf16x3 split)
    qkv_gemm_tc<<<dim3(HWN/BN, CH/BM, 3*BATCH), 256, GEMM_SMEM>>>();
    // 2. depthwise 3x3 (4 px/thread, fused sqnorm partials)
    dwconv_kernel<<<dim3(1, IMG/8, 3*BATCH*CH), dim3(32,8)>>>(w_dw);
    // 3. reduce sqnorm partials
    sqnorm_kernel<<<(2*BATCH*CH + 255)/256, 256>>>();
    // 4-5. Gram (two-phase deterministic)
    gram_kernel<<<dim3(GRAM_CHUNKS, NBH), dim3(16,16)>>>();
    gram_reduce_kernel<<<(NBH*HD*HD)/1024, 1024>>>();
    // 6. softmax
    softmax_kernel<<<NBH, 64>>>(temp);
    // 7. A@V (emits bf16 hi/lo, transposed)
    av_kernel<<<dim3(HWN/256, NBH), 256>>>();
    // 8. output projection on tensor cores
    proj_gemm_tc<<<dim3(HWN/BN, CH/BM, BATCH), 256, GEMM_SMEM>>>(out);
}